// round 4
// baseline (speedup 1.0000x reference)
#include <cuda_runtime.h>

// NormSelfAttention: B=4,H=16,N=2048,D=128
//   Qf = elu(Q)+1 ; Kf = (elu(K)+1)*mask ; Vf = V*mask
//   KV[d,e] = sum_n Kf[n,d]*Vf[n,e] ; out[n,e] = sum_d Qf[n,d]*KV[d,e]
//   out = out * rsqrt(mean_e(out^2) + 1e-6)

#define HH     16
#define BH     64
#define SEQ    2048
#define DD     128
#define SPLITS 8
#define NSPLIT (SEQ / SPLITS)   // 256
#define CHUNK  16

// Scratch (device globals: allocation rules forbid cudaMalloc)
__device__ float g_kvpart[(size_t)BH * SPLITS * DD * DD];  // 32 MB
__device__ float g_kv[(size_t)BH * DD * DD];               //  4 MB

typedef unsigned long long u64_t;

static __device__ __forceinline__ u64_t pk2(float a, float b) {
    u64_t r;
    asm("mov.b64 %0, {%1, %2};"
        : "=l"(r) : "r"(__float_as_uint(a)), "r"(__float_as_uint(b)));
    return r;
}
static __device__ __forceinline__ u64_t ffma2(u64_t a, u64_t b, u64_t c) {
    u64_t d;
    asm("fma.rn.f32x2 %0, %1, %2, %3;" : "=l"(d) : "l"(a), "l"(b), "l"(c));
    return d;
}
static __device__ __forceinline__ void upk2(u64_t v, float& lo, float& hi) {
    unsigned int l, h;
    asm("mov.b64 {%0, %1}, %2;" : "=r"(l), "=r"(h) : "l"(v));
    lo = __uint_as_float(l);
    hi = __uint_as_float(h);
}
static __device__ __forceinline__ float actf(float x) {
    // elu(x)+1 : x>0 -> x+1 ; else exp(x)
    return x > 0.0f ? x + 1.0f : __expf(x);
}

// ---------------------------------------------------------------------------
// Phase 1: KV partials. grid (SPLITS, BH), 256 threads.
// Block computes full 128x128 KV over its 256-row n-slice.
// Thread microtile: 8 e (j, broadcast side) x 8 d (as 4 f32x2 pairs).
// ---------------------------------------------------------------------------
__global__ __launch_bounds__(256, 2)
void kv_kernel(const float* __restrict__ K, const float* __restrict__ V,
               const float* __restrict__ mask) {
    const int split = blockIdx.x;
    const int bh    = blockIdx.y;
    const int b     = bh >> 4;           // H = 16
    const int nbase = split * NSPLIT;

    __shared__ float4 Ks[CHUNK][32];     // [n][d/4]
    __shared__ float4 Vs[CHUNK][32];     // [n][e/4]

    const int tid = threadIdx.x;
    const int tx  = tid & 15;            // e group
    const int ty  = tid >> 4;            // d group
    const int e0  = tx * 8;
    const int d0  = ty * 8;

    u64_t acc[8][4];
#pragma unroll
    for (int j = 0; j < 8; j++)
#pragma unroll
        for (int p = 0; p < 4; p++) acc[j][p] = 0ull;

    const float4* K4 = ((const float4*)K) + (size_t)bh * (SEQ * DD / 4);
    const float4* V4 = ((const float4*)V) + (size_t)bh * (SEQ * DD / 4);
    const float*  mrow = mask + b * SEQ;

    for (int c = 0; c < NSPLIT; c += CHUNK) {
        __syncthreads();
#pragma unroll
        for (int it = 0; it < 2; it++) {
            int flat = tid + it * 256;       // 512 float4 per operand
            int row  = flat >> 5;
            int col  = flat & 31;
            int n    = nbase + c + row;
            float m  = mrow[n];
            float4 kv = K4[(size_t)n * 32 + col];
            kv.x = actf(kv.x) * m; kv.y = actf(kv.y) * m;
            kv.z = actf(kv.z) * m; kv.w = actf(kv.w) * m;
            Ks[row][col] = kv;
            float4 vv = V4[(size_t)n * 32 + col];
            vv.x *= m; vv.y *= m; vv.z *= m; vv.w *= m;
            Vs[row][col] = vv;
        }
        __syncthreads();
#pragma unroll
        for (int n = 0; n < CHUNK; n++) {
            float4 ka = Ks[n][ty * 2];
            float4 kb = Ks[n][ty * 2 + 1];
            float4 va = Vs[n][tx * 2];
            float4 vb = Vs[n][tx * 2 + 1];
            u64_t kp[4] = { pk2(ka.x, ka.y), pk2(ka.z, ka.w),
                            pk2(kb.x, kb.y), pk2(kb.z, kb.w) };
            float vf[8] = { va.x, va.y, va.z, va.w, vb.x, vb.y, vb.z, vb.w };
#pragma unroll
            for (int j = 0; j < 8; j++) {
                u64_t vj = pk2(vf[j], vf[j]);
#pragma unroll
                for (int p = 0; p < 4; p++)
                    acc[j][p] = ffma2(vj, kp[p], acc[j][p]);
            }
        }
    }

    // acc[j][p] = ( KV[d0+2p][e0+j] , KV[d0+2p+1][e0+j] )
    float* out = g_kvpart + ((size_t)bh * SPLITS + split) * (DD * DD);
#pragma unroll
    for (int p = 0; p < 4; p++) {
        float lo[8], hi[8];
#pragma unroll
        for (int j = 0; j < 8; j++) upk2(acc[j][p], lo[j], hi[j]);
        float* r0 = out + (size_t)(d0 + 2 * p)     * DD + e0;
        float* r1 = out + (size_t)(d0 + 2 * p + 1) * DD + e0;
        *(float4*)(r0)     = make_float4(lo[0], lo[1], lo[2], lo[3]);
        *(float4*)(r0 + 4) = make_float4(lo[4], lo[5], lo[6], lo[7]);
        *(float4*)(r1)     = make_float4(hi[0], hi[1], hi[2], hi[3]);
        *(float4*)(r1 + 4) = make_float4(hi[4], hi[5], hi[6], hi[7]);
    }
}

// ---------------------------------------------------------------------------
// Phase 1.5: reduce 8 split partials -> g_kv. 262144 float4 total.
// ---------------------------------------------------------------------------
__global__ __launch_bounds__(256)
void reduce_kernel() {
    int idx = blockIdx.x * 256 + threadIdx.x;      // over float4 of g_kv
    const float4* in  = (const float4*)g_kvpart;
    float4*       out = (float4*)g_kv;
    int bh  = idx >> 12;                           // 4096 float4 per bh
    int off = idx & 4095;
    float4 s = make_float4(0.f, 0.f, 0.f, 0.f);
#pragma unroll
    for (int sp = 0; sp < SPLITS; sp++) {
        float4 v = in[((size_t)bh * SPLITS + sp) * 4096 + off];
        s.x += v.x; s.y += v.y; s.z += v.z; s.w += v.w;
    }
    out[idx] = s;
}

// ---------------------------------------------------------------------------
// Phase 2: out = Qf @ KV + fused RMS norm. grid (16, BH), 256 threads.
// Smem: Qs[128][130] (pad 130 -> 8-row stride hits distinct banks),
//       KVs[128][128] (float4), red[128][16], scale[128]. ~137.5 KB dynamic.
// Thread microtile: 8 n (i, broadcast side) x 8 e (4 f32x2 pairs).
// ---------------------------------------------------------------------------
#define QPAD 130
#define SMEM2_FLOATS (128 * QPAD + 128 * 128 + 128 * 16 + 128)
#define SMEM2_BYTES  (SMEM2_FLOATS * 4)

__global__ __launch_bounds__(256)
void out_kernel(const float* __restrict__ Q, float* __restrict__ O) {
    const int ntile = blockIdx.x;
    const int bh    = blockIdx.y;
    const int n0t   = ntile * 128;
    const int tid   = threadIdx.x;
    const int tx    = tid & 15;          // e group
    const int ty    = tid >> 4;          // n group
    const int e0    = tx * 8;
    const int nl0   = ty * 8;

    extern __shared__ float sm[];
    float*  Qs    = sm;                               // 128*130
    float4* KVs   = (float4*)(sm + 128 * QPAD);       // 128*32 float4
    float*  red   = sm + 128 * QPAD + 128 * 128;      // 128*16
    float*  scale = red + 128 * 16;                   // 128

    // Load KV tile (already reduced)
    const float4* kvg = ((const float4*)g_kv) + (size_t)bh * (DD * DD / 4);
#pragma unroll
    for (int it = 0; it < 16; it++)
        KVs[tid + it * 256] = kvg[tid + it * 256];

    // Load + activate Q tile into padded smem (coalesced gmem read)
    const float4* Q4 = ((const float4*)Q) + ((size_t)bh * SEQ + n0t) * (DD / 4);
#pragma unroll
    for (int it = 0; it < 16; it++) {
        int flat = tid + it * 256;       // 4096 float4
        int row  = flat >> 5;
        int col  = flat & 31;
        float4 q = Q4[flat];
        float* dst = Qs + row * QPAD + col * 4;
        dst[0] = actf(q.x); dst[1] = actf(q.y);
        dst[2] = actf(q.z); dst[3] = actf(q.w);
    }
    __syncthreads();

    u64_t acc[8][4];
#pragma unroll
    for (int i = 0; i < 8; i++)
#pragma unroll
        for (int p = 0; p < 4; p++) acc[i][p] = 0ull;

#pragma unroll 4
    for (int d = 0; d < DD; d++) {
        float4 ca = KVs[d * 32 + tx * 2];
        float4 cb = KVs[d * 32 + tx * 2 + 1];
        u64_t cp[4] = { pk2(ca.x, ca.y), pk2(ca.z, ca.w),
                        pk2(cb.x, cb.y), pk2(cb.z, cb.w) };
#pragma unroll
        for (int i = 0; i < 8; i++) {
            float qv = Qs[(nl0 + i) * QPAD + d];
            u64_t qp = pk2(qv, qv);
#pragma unroll
            for (int p = 0; p < 4; p++)
                acc[i][p] = ffma2(qp, cp[p], acc[i][p]);
        }
    }

    // Partial sum-of-squares per row -> smem reduce across 16 tx threads
#pragma unroll
    for (int i = 0; i < 8; i++) {
        float ss = 0.f;
#pragma unroll
        for (int p = 0; p < 4; p++) {
            float lo, hi; upk2(acc[i][p], lo, hi);
            ss += lo * lo + hi * hi;
        }
        red[(nl0 + i) * 16 + tx] = ss;
    }
    __syncthreads();
    if (tid < 128) {
        float s = 0.f;
#pragma unroll
        for (int j = 0; j < 16; j++) s += red[tid * 16 + j];
        scale[tid] = rsqrtf(s * (1.0f / 128.0f) + 1e-6f);
    }
    __syncthreads();

    float* Obase = O + ((size_t)bh * SEQ + n0t) * DD;
#pragma unroll
    for (int i = 0; i < 8; i++) {
        float sc = scale[nl0 + i];
        float* orow = Obase + (size_t)(nl0 + i) * DD + e0;
#pragma unroll
        for (int p = 0; p < 4; p++) {
            float lo, hi; upk2(acc[i][p], lo, hi);
            *(float2*)(orow + 2 * p) = make_float2(lo * sc, hi * sc);
        }
    }
}

// ---------------------------------------------------------------------------
extern "C" void kernel_launch(void* const* d_in, const int* in_sizes, int n_in,
                              void* d_out, int out_size) {
    const float* Q    = (const float*)d_in[0];
    const float* K    = (const float*)d_in[1];
    const float* V    = (const float*)d_in[2];
    const float* mask = (const float*)d_in[3];
    float*       O    = (float*)d_out;

    // Opt-in to >48KB dynamic smem for phase 2 (idempotent; host-side, legal
    // during graph capture since it is not a stream operation).
    cudaFuncSetAttribute(out_kernel, cudaFuncAttributeMaxDynamicSharedMemorySize,
                         SMEM2_BYTES);

    kv_kernel<<<dim3(SPLITS, BH), 256>>>(K, V, mask);
    reduce_kernel<<<(BH * DD * DD / 4) / 256, 256>>>();
    out_kernel<<<dim3(SEQ / 128, BH), 256, SMEM2_BYTES>>>(Q, O);
}